// round 7
// baseline (speedup 1.0000x reference)
#include <cuda_runtime.h>
#include <cuda_bf16.h>

#define NN    8192
#define NE    65536
#define FEAT  136
#define WN    3392
#define SW_LD 68   // 64 rows + pad, 272B stride = 16B aligned per column

__device__ float g_accum[NN * FEAT];
__device__ float g_cnt[NN];

// ---------------- packed f32x2 helpers ----------------
__device__ __forceinline__ unsigned long long fma2(unsigned long long a,
                                                   unsigned long long b,
                                                   unsigned long long c) {
    unsigned long long d;
    asm("fma.rn.f32x2 %0, %1, %2, %3;" : "=l"(d) : "l"(a), "l"(b), "l"(c));
    return d;
}
__device__ __forceinline__ unsigned long long add2(unsigned long long a,
                                                   unsigned long long b) {
    unsigned long long d;
    asm("add.rn.f32x2 %0, %1, %2;" : "=l"(d) : "l"(a), "l"(b));
    return d;
}
__device__ __forceinline__ float2 unpack2(unsigned long long v) {
    float2 r;
    asm("mov.b64 {%0, %1}, %2;" : "=f"(r.x), "=f"(r.y) : "l"(v));
    return r;
}
__device__ __forceinline__ unsigned long long pack2(float lo, float hi) {
    unsigned long long r;
    asm("mov.b64 %0, {%1, %2};" : "=l"(r) : "f"(lo), "f"(hi));
    return r;
}

// 64-element dot: h (32 f32x2 pairs, registers) vs one SMEM column (contiguous,
// 16B aligned). 4 independent accumulator chains for ILP.
__device__ __forceinline__ float dot64(const unsigned long long* h2, const float* col) {
    const ulonglong2* c4 = reinterpret_cast<const ulonglong2*>(col);
    unsigned long long a0 = 0ull, a1 = 0ull, a2 = 0ull, a3 = 0ull;
#pragma unroll
    for (int k = 0; k < 8; k++) {
        ulonglong2 vA = c4[2*k];
        ulonglong2 vB = c4[2*k + 1];
        a0 = fma2(h2[4*k + 0], vA.x, a0);
        a1 = fma2(h2[4*k + 1], vA.y, a1);
        a2 = fma2(h2[4*k + 2], vB.x, a2);
        a3 = fma2(h2[4*k + 3], vB.y, a3);
    }
    a0 = add2(a0, a1);
    a2 = add2(a2, a3);
    a0 = add2(a0, a2);
    float2 f = unpack2(a0);
    return f.x + f.y;
}

// Stage 64 columns x 64 rows of g[row*ld + col0 + c] transposed into
// sW[c*SW_LD + row]. Coalesced global reads (64 consecutive floats per row seg).
__device__ __forceinline__ void stage64(const float* __restrict__ g, int ld,
                                        int col0, float* sW, int tid) {
#pragma unroll
    for (int r = 0; r < 32; r++) {
        int p   = r * 128 + tid;
        int row = p >> 6;
        int c   = p & 63;
        sW[c * SW_LD + row] = g[row * ld + col0 + c];
    }
}

__global__ void zero_kernel() {
    int idx = blockIdx.x * 256 + threadIdx.x;
    if (idx < NN * FEAT) g_accum[idx] = 0.0f;
    if (idx < NN)        g_cnt[idx]   = 0.0f;
}

__global__ void __launch_bounds__(128, 4) tp_edge_kernel(
    const float* __restrict__ node_attr,
    const int*   __restrict__ edge_index,
    const float* __restrict__ edge_attr,
    const float* __restrict__ edge_sh,
    const float* __restrict__ fc_w1,
    const float* __restrict__ fc_b1,
    const float* __restrict__ fc_w2,
    const float* __restrict__ fc_b2)
{
    __shared__ float sW[64 * SW_LD];   // staged (transposed) weight chunk
    __shared__ float sY[48 * 128];     // per-thread output accumulators

    const int tid = threadIdx.x;
    const int e   = blockIdx.x * 128 + tid;   // grid exactly covers NE
    const int src = edge_index[e];
    const int dst = edge_index[NE + e];

    // ---------- h = relu(ea @ W1 + b1), kept in regs as f32x2 pairs ----------
    unsigned long long ea2[32];
    {
        const ulonglong2* g = reinterpret_cast<const ulonglong2*>(edge_attr + (size_t)e * 64);
#pragma unroll
        for (int k = 0; k < 16; k++) { ulonglong2 v = g[k]; ea2[2*k] = v.x; ea2[2*k+1] = v.y; }
    }
    stage64(fc_w1, 64, 0, sW, tid);
    __syncthreads();

    unsigned long long h2[32];
#pragma unroll
    for (int jp = 0; jp < 32; jp++) {
        float v0 = dot64(ea2, &sW[(2*jp    ) * SW_LD]) + fc_b1[2*jp];
        float v1 = dot64(ea2, &sW[(2*jp + 1) * SW_LD]) + fc_b1[2*jp + 1];
        h2[jp] = pack2(fmaxf(v0, 0.0f), fmaxf(v1, 0.0f));
    }

    const float* na  = node_attr + (size_t)dst * FEAT;
    const float4 shv = *reinterpret_cast<const float4*>(edge_sh + 4 * (size_t)e);
    const float sh0 = shv.x, s1x = shv.y, s1y = shv.z, s1z = shv.w;
    const float INV_S3 = 0.57735026918962576f;
    const float INV_S2 = 0.70710678118654752f;

    atomicAdd(&g_cnt[src], 1.0f);

    float oarr[192];                       // per-thread local (uniform offsets)
    float* yacc = &g_accum[(size_t)src * FEAT];

    // ============ phase 0e : cols [0,1536), in=48, out=32 ============
    {
#pragma unroll 1
        for (int i = 0; i < 32; i++) oarr[i] = na[i] * sh0;
#pragma unroll 1
        for (int m = 0; m < 16; m++) {
            float a0 = na[32+3*m], a1 = na[33+3*m], a2 = na[34+3*m];
            oarr[32+m] = (a0*s1x + a1*s1y + a2*s1z) * INV_S3;
        }
#pragma unroll 1
        for (int o = 0; o < 32; o++) sY[o*128 + tid] = 0.0f;
#pragma unroll 1
        for (int ch = 0; ch < 24; ch++) {
            __syncthreads();
            stage64(fc_w2, WN, ch*64, sW, tid);
            __syncthreads();
#pragma unroll 1
            for (int jc = 0; jc < 64; jc++) {
                int j = ch*64 + jc;
                float w = dot64(h2, &sW[jc * SW_LD]) + fc_b2[j];
                sY[(j & 31)*128 + tid] += oarr[j >> 5] * w;
            }
        }
#pragma unroll 1
        for (int o = 0; o < 32; o++)
            atomicAdd(yacc + o, sY[o*128 + tid] * 0.14433756729740643f);   // 1/sqrt(48)
    }

    // ============ phase 1o : cols [1536,2560), in=64 vec, out=16 ============
    {
#pragma unroll 1
        for (int i = 0; i < 32; i++) {
            float t = na[i];
            oarr[3*i] = t*s1x; oarr[3*i+1] = t*s1y; oarr[3*i+2] = t*s1z;
        }
#pragma unroll 1
        for (int m = 0; m < 16; m++) {
            int i = 32 + m;
            oarr[3*i]   = na[32+3*m] * sh0;
            oarr[3*i+1] = na[33+3*m] * sh0;
            oarr[3*i+2] = na[34+3*m] * sh0;
        }
#pragma unroll 1
        for (int m = 0; m < 16; m++) {
            int i = 48 + m;
            float a0 = na[80+3*m], a1 = na[81+3*m], a2 = na[82+3*m];
            oarr[3*i+0] = (a1*s1z - a2*s1y) * INV_S2;
            oarr[3*i+1] = (a2*s1x - a0*s1z) * INV_S2;
            oarr[3*i+2] = (a0*s1y - a1*s1x) * INV_S2;
        }
#pragma unroll 1
        for (int q = 0; q < 48; q++) sY[q*128 + tid] = 0.0f;
#pragma unroll 1
        for (int ch = 0; ch < 16; ch++) {
            __syncthreads();
            stage64(fc_w2, WN, 1536 + ch*64, sW, tid);
            __syncthreads();
#pragma unroll 1
            for (int jc = 0; jc < 64; jc++) {
                int jj = ch*64 + jc;
                float w = dot64(h2, &sW[jc * SW_LD]) + fc_b2[1536 + jj];
                int i = jj >> 4;
                float* yb = &sY[((jj & 15) * 3) * 128 + tid];
                yb[0]   += oarr[3*i    ] * w;
                yb[128] += oarr[3*i + 1] * w;
                yb[256] += oarr[3*i + 2] * w;
            }
        }
#pragma unroll 1
        for (int q = 0; q < 48; q++)
            atomicAdd(yacc + 32 + q, sY[q*128 + tid] * 0.125f);            // 1/sqrt(64)
    }

    // ============ phase 1e : cols [2560,3200), in=40 vec, out=16 ============
    {
#pragma unroll 1
        for (int m = 0; m < 16; m++) {                 // cross(x1o, sh1)/sqrt2
            float a0 = na[32+3*m], a1 = na[33+3*m], a2 = na[34+3*m];
            oarr[3*m+0] = (a1*s1z - a2*s1y) * INV_S2;
            oarr[3*m+1] = (a2*s1x - a0*s1z) * INV_S2;
            oarr[3*m+2] = (a0*s1y - a1*s1x) * INV_S2;
        }
#pragma unroll 1
        for (int m = 0; m < 16; m++) {                 // x1e * sh0
            int i = 16 + m;
            oarr[3*i]   = na[80+3*m] * sh0;
            oarr[3*i+1] = na[81+3*m] * sh0;
            oarr[3*i+2] = na[82+3*m] * sh0;
        }
#pragma unroll 1
        for (int m = 0; m < 8; m++) {                  // x0o outer sh1
            int i = 32 + m; float t = na[128+m];
            oarr[3*i] = t*s1x; oarr[3*i+1] = t*s1y; oarr[3*i+2] = t*s1z;
        }
#pragma unroll 1
        for (int q = 0; q < 48; q++) sY[q*128 + tid] = 0.0f;
#pragma unroll 1
        for (int ch = 0; ch < 10; ch++) {
            __syncthreads();
            stage64(fc_w2, WN, 2560 + ch*64, sW, tid);
            __syncthreads();
#pragma unroll 1
            for (int jc = 0; jc < 64; jc++) {
                int jj = ch*64 + jc;
                float w = dot64(h2, &sW[jc * SW_LD]) + fc_b2[2560 + jj];
                int i = jj >> 4;
                float* yb = &sY[((jj & 15) * 3) * 128 + tid];
                yb[0]   += oarr[3*i    ] * w;
                yb[128] += oarr[3*i + 1] * w;
                yb[256] += oarr[3*i + 2] * w;
            }
        }
#pragma unroll 1
        for (int q = 0; q < 48; q++)
            atomicAdd(yacc + 80 + q, sY[q*128 + tid] * 0.15811388300841897f); // 1/sqrt(40)
    }

    // ============ phase 0o : cols [3200,3392), in=24, out=8 ============
    {
#pragma unroll 1
        for (int m = 0; m < 16; m++) {                 // dot(x1e, sh1)/sqrt3
            float a0 = na[80+3*m], a1 = na[81+3*m], a2 = na[82+3*m];
            oarr[m] = (a0*s1x + a1*s1y + a2*s1z) * INV_S3;
        }
#pragma unroll 1
        for (int m = 0; m < 8; m++) oarr[16+m] = na[128+m] * sh0;
#pragma unroll 1
        for (int o = 0; o < 8; o++) sY[o*128 + tid] = 0.0f;
#pragma unroll 1
        for (int ch = 0; ch < 3; ch++) {
            __syncthreads();
            stage64(fc_w2, WN, 3200 + ch*64, sW, tid);
            __syncthreads();
#pragma unroll 1
            for (int jc = 0; jc < 64; jc++) {
                int jj = ch*64 + jc;
                float w = dot64(h2, &sW[jc * SW_LD]) + fc_b2[3200 + jj];
                sY[(jj & 7)*128 + tid] += oarr[jj >> 3] * w;
            }
        }
#pragma unroll 1
        for (int o = 0; o < 8; o++)
            atomicAdd(yacc + 128 + o, sY[o*128 + tid] * 0.20412414523193150f); // 1/sqrt(24)
    }
}

__global__ void finalize_kernel(const float* __restrict__ node_attr,
                                float* __restrict__ out) {
    int idx = blockIdx.x * 256 + threadIdx.x;
    if (idx < NN * FEAT) {
        int n = idx / FEAT;
        out[idx] = node_attr[idx] + g_accum[idx] / fmaxf(g_cnt[n], 1.0f);
    }
}

extern "C" void kernel_launch(void* const* d_in, const int* in_sizes, int n_in,
                              void* d_out, int out_size) {
    const float* node_attr  = (const float*)d_in[0];
    const int*   edge_index = (const int*)  d_in[1];
    const float* edge_attr  = (const float*)d_in[2];
    const float* edge_sh    = (const float*)d_in[3];
    const float* fc_w1      = (const float*)d_in[4];
    const float* fc_b1      = (const float*)d_in[5];
    const float* fc_w2      = (const float*)d_in[6];
    const float* fc_b2      = (const float*)d_in[7];
    float* out = (float*)d_out;

    zero_kernel<<<(NN * FEAT + 255) / 256, 256>>>();
    tp_edge_kernel<<<NE / 128, 128>>>(node_attr, edge_index, edge_attr, edge_sh,
                                      fc_w1, fc_b1, fc_w2, fc_b2);
    finalize_kernel<<<(NN * FEAT + 255) / 256, 256>>>(node_attr, out);
}